// round 1
// baseline (speedup 1.0000x reference)
#include <cuda_runtime.h>
#include <cuda_bf16.h>
#include <math_constants.h>
#include <cstdint>

// Problem shape (fixed by the dataset)
#define TB 8
#define TT 2048
#define TC 1024
#define TM_TOTAL (TB*TT)      // 16384 rows

// -------------------- scratch (no allocations allowed) --------------------
__device__ float g_buf0[TB * TC * TT];   // q_t [B,C,T]  -> attn_t [B,C,T] -> h2 [B,T,C]
__device__ float g_buf1[TB * TC * TT];   // k_t [B,C,T]  -> attn   [B,T,C]
__device__ float g_y1  [TB * TT * TC];   // LN1 output
__device__ float g_h1  [TB * TT * TC];   // relu(y1@W1+bf1)
__device__ float g_vsum[TB * TT];        // sum_c v[b,t,c]
__device__ float g_wvs [TC + 1];         // rowsum(Wv) plus sum(bv) at [TC]

// -------------------- block reductions (256 threads) --------------------
__device__ __forceinline__ float blk_reduce_sum(float v, float* sbuf) {
    #pragma unroll
    for (int o = 16; o; o >>= 1) v += __shfl_xor_sync(0xffffffffu, v, o);
    if ((threadIdx.x & 31) == 0) sbuf[threadIdx.x >> 5] = v;
    __syncthreads();
    if (threadIdx.x < 32) {
        float w = (threadIdx.x < 8) ? sbuf[threadIdx.x] : 0.0f;
        #pragma unroll
        for (int o = 4; o; o >>= 1) w += __shfl_xor_sync(0xffffffffu, w, o);
        if (threadIdx.x == 0) sbuf[0] = w;
    }
    __syncthreads();
    float r = sbuf[0];
    __syncthreads();
    return r;
}

__device__ __forceinline__ float blk_reduce_max(float v, float* sbuf) {
    #pragma unroll
    for (int o = 16; o; o >>= 1) v = fmaxf(v, __shfl_xor_sync(0xffffffffu, v, o));
    if ((threadIdx.x & 31) == 0) sbuf[threadIdx.x >> 5] = v;
    __syncthreads();
    if (threadIdx.x < 32) {
        float w = (threadIdx.x < 8) ? sbuf[threadIdx.x] : -CUDART_INF_F;
        #pragma unroll
        for (int o = 4; o; o >>= 1) w = fmaxf(w, __shfl_xor_sync(0xffffffffu, w, o));
        if (threadIdx.x == 0) sbuf[0] = w;
    }
    __syncthreads();
    float r = sbuf[0];
    __syncthreads();
    return r;
}

// -------------------- SGEMM: C = A[MxK] @ B[KxN] + bias, opt relu, opt transposed-out --------------------
#define BM 128
#define BN 128
#define BK 8
#define RTM 8
#define RTN 8

template<int TRANS_OUT, int RELU>
__global__ void __launch_bounds__(256, 2)
sgemm_kernel(const float* __restrict__ A, const float* __restrict__ Bmat,
             const float* __restrict__ bias, float* C,
             int M, int N, int K)
{
    __shared__ float As[BK][BM];
    __shared__ float Bs[BK][BN];

    const int m0 = blockIdx.y * BM;
    const int n0 = blockIdx.x * BN;
    const int tid = threadIdx.x;
    const int tx = tid & 15;
    const int ty = tid >> 4;

    const int aRow = tid >> 1;          // 0..127
    const int aCol = (tid & 1) * 4;     // 0 or 4
    const int bRow = tid >> 5;          // 0..7
    const int bCol = (tid & 31) * 4;    // 0..124

    const float* Ap = A + (size_t)(m0 + aRow) * K + aCol;
    const float* Bp = Bmat + (size_t)bRow * N + (n0 + bCol);

    float acc[RTM][RTN];
    #pragma unroll
    for (int i = 0; i < RTM; i++)
        #pragma unroll
        for (int j = 0; j < RTN; j++) acc[i][j] = 0.0f;

    for (int k0 = 0; k0 < K; k0 += BK) {
        float4 av = *(const float4*)(Ap + k0);
        float4 bv = *(const float4*)(Bp + (size_t)k0 * N);
        As[aCol + 0][aRow] = av.x;
        As[aCol + 1][aRow] = av.y;
        As[aCol + 2][aRow] = av.z;
        As[aCol + 3][aRow] = av.w;
        *(float4*)&Bs[bRow][bCol] = bv;
        __syncthreads();

        #pragma unroll
        for (int kk = 0; kk < BK; kk++) {
            float a[RTM], b[RTN];
            #pragma unroll
            for (int i = 0; i < RTM; i++) a[i] = As[kk][ty * RTM + i];
            #pragma unroll
            for (int j = 0; j < RTN; j++) b[j] = Bs[kk][tx * RTN + j];
            #pragma unroll
            for (int i = 0; i < RTM; i++)
                #pragma unroll
                for (int j = 0; j < RTN; j++) acc[i][j] += a[i] * b[j];
        }
        __syncthreads();
    }

    float bb[RTN];
    #pragma unroll
    for (int j = 0; j < RTN; j++) bb[j] = bias[n0 + tx * RTN + j];

    if (TRANS_OUT) {
        // output layout [B, N, T]; m = b*TT + t (BM=128 divides TT, tile within one b)
        #pragma unroll
        for (int j = 0; j < RTN; j++) {
            int n = n0 + tx * RTN + j;
            #pragma unroll
            for (int i = 0; i < RTM; i++) {
                int m = m0 + ty * RTM + i;
                int bbi = m >> 11;          // /TT
                int t   = m & (TT - 1);
                float v = acc[i][j] + bb[j];
                C[((size_t)bbi * TC + n) * TT + t] = v;
            }
        }
    } else {
        #pragma unroll
        for (int i = 0; i < RTM; i++) {
            int m = m0 + ty * RTM + i;
            float* crow = C + (size_t)m * N + n0 + tx * RTN;
            float v[RTN];
            #pragma unroll
            for (int j = 0; j < RTN; j++) {
                v[j] = acc[i][j] + bb[j];
                if (RELU) v[j] = fmaxf(v[j], 0.0f);
            }
            *(float4*)(crow)     = make_float4(v[0], v[1], v[2], v[3]);
            *(float4*)(crow + 4) = make_float4(v[4], v[5], v[6], v[7]);
        }
    }
}

// -------------------- wvsum: rowsum(Wv) and sum(bv) --------------------
__global__ void wvsum_kernel(const float* __restrict__ Wv, const float* __restrict__ bv,
                             float* __restrict__ out)
{
    __shared__ float sbuf[32];
    int d = blockIdx.x;                 // 0..TC (last = bv)
    const float* src = (d < TC) ? (Wv + (size_t)d * TC) : bv;
    float s = 0.0f;
    for (int c = threadIdx.x; c < TC; c += 256) s += src[c];
    s = blk_reduce_sum(s, sbuf);
    if (threadIdx.x == 0) out[d] = s;
}

// -------------------- vsum[m] = dot(x[m,:], wvs) + wvs[TC] --------------------
__global__ void vsum_kernel(const float* __restrict__ x, const float* __restrict__ wvs,
                            float* __restrict__ out)
{
    __shared__ float sbuf[32];
    int row = blockIdx.x;
    const float* xr = x + (size_t)row * TC;
    float s = 0.0f;
    for (int c = threadIdx.x; c < TC; c += 256) s += xr[c] * wvs[c];
    s = blk_reduce_sum(s, sbuf);
    if (threadIdx.x == 0) out[row] = s + wvs[TC];
}

// -------------------- FFT stages (in-place DIT, input bit-reversed, output natural) --------------------
__device__ __forceinline__ void fft_stages(float2* z, const float2* tw, int tid, bool inverse)
{
    #pragma unroll
    for (int s = 1; s <= 11; s++) {
        int half = 1 << (s - 1);
        int tshift = 11 - s;
        for (int j = tid; j < 1024; j += 256) {
            int grp = j >> (s - 1);
            int pos = j & (half - 1);
            int i1 = (grp << s) + pos;
            int i2 = i1 + half;
            float2 w = tw[pos << tshift];
            if (inverse) w.y = -w.y;
            float2 u = z[i1];
            float2 v = z[i2];
            float tr = w.x * v.x - w.y * v.y;
            float ti = w.x * v.y + w.y * v.x;
            z[i1] = make_float2(u.x + tr, u.y + ti);
            z[i2] = make_float2(u.x - tr, u.y - ti);
        }
        __syncthreads();
    }
}

// -------------------- FFT correlation + softmax + *vsum, per (b,c) row --------------------
// reads q_t,k_t [B,C,T]; writes attn_t [B,C,T] (may alias q_t: row fully staged in smem first)
__global__ void __launch_bounds__(256)
fft_corr_softmax(const float* qt, const float* kt,
                 const float* __restrict__ vsum, float* attn_t)
{
    __shared__ float2 z[2048];
    __shared__ float2 tw[1024];
    __shared__ float sbuf[32];

    const int bc = blockIdx.x;          // b*TC + c
    const int b = bc >> 10;
    const int tid = threadIdx.x;
    const float* qrow = qt + (size_t)bc * TT;
    const float* krow = kt + (size_t)bc * TT;

    for (int j = tid; j < 1024; j += 256) {
        float sv, cv;
        sincosf(-6.283185307179586f * ((float)j * (1.0f / 2048.0f)), &sv, &cv);
        tw[j] = make_float2(cv, sv);
    }
    // load z = q + i*k, bit-reversed
    for (int t = tid; t < 2048; t += 256) {
        int r = __brev((unsigned)t) >> 21;
        z[r] = make_float2(qrow[t], krow[t]);
    }
    __syncthreads();

    fft_stages(z, tw, tid, false);      // forward, natural-order spectrum

    // P(f) = Q(f) * conj(K(f)); Hermitian split of packed transform
    for (int f = tid; f <= 1024; f += 256) {
        int g = (2048 - f) & 2047;
        float2 zf = z[f], zg = z[g];
        float Qr = 0.5f * (zf.x + zg.x);
        float Qi = 0.5f * (zf.y - zg.y);
        float Kr = 0.5f * (zf.y + zg.y);
        float Ki = 0.5f * (zg.x - zf.x);
        float Pr = Qr * Kr + Qi * Ki;
        float Pi = Qi * Kr - Qr * Ki;
        z[f] = make_float2(Pr, Pi);
        z[g] = make_float2(Pr, -Pi);
    }
    __syncthreads();

    // bit-reverse permute, then inverse transform
    for (int t = tid; t < 2048; t += 256) {
        int r = __brev((unsigned)t) >> 21;
        if (r > t) { float2 a = z[t]; z[t] = z[r]; z[r] = a; }
    }
    __syncthreads();
    fft_stages(z, tw, tid, true);

    // corr[t] = Re(z[t]) / N ; softmax over t; attn = w * vsum[b,t]
    float cvals[8];
    float vmax = -CUDART_INF_F;
    #pragma unroll
    for (int i = 0; i < 8; i++) {
        int t = tid + i * 256;
        cvals[i] = z[t].x * (1.0f / 2048.0f);
        vmax = fmaxf(vmax, cvals[i]);
    }
    vmax = blk_reduce_max(vmax, sbuf);
    float ssum = 0.0f;
    #pragma unroll
    for (int i = 0; i < 8; i++) {
        cvals[i] = expf(cvals[i] - vmax);
        ssum += cvals[i];
    }
    ssum = blk_reduce_sum(ssum, sbuf);
    float inv = 1.0f / ssum;

    const float* vs = vsum + (size_t)b * TT;
    float* arow = attn_t + (size_t)bc * TT;
    #pragma unroll
    for (int i = 0; i < 8; i++) {
        int t = tid + i * 256;
        arow[t] = cvals[i] * inv * vs[t];
    }
}

// -------------------- transpose [B,C,T] -> [B,T,C] --------------------
__global__ void transpose_kernel(const float* __restrict__ in, float* __restrict__ out)
{
    __shared__ float tile[32][33];
    int b = blockIdx.z;
    int t0 = blockIdx.x * 32;
    int c0 = blockIdx.y * 32;
    const float* inb = in + (size_t)b * TC * TT;
    float* outb = out + (size_t)b * TT * TC;
    #pragma unroll
    for (int y = threadIdx.y; y < 32; y += 8)
        tile[y][threadIdx.x] = inb[(size_t)(c0 + y) * TT + t0 + threadIdx.x];
    __syncthreads();
    #pragma unroll
    for (int y = threadIdx.y; y < 32; y += 8)
        outb[(size_t)(t0 + y) * TC + c0 + threadIdx.x] = tile[threadIdx.x][y];
}

// -------------------- residual + layernorm --------------------
__global__ void __launch_bounds__(256)
add_ln_kernel(const float* __restrict__ x, const float* __restrict__ r,
              const float* __restrict__ g, const float* __restrict__ be,
              float* __restrict__ out)
{
    __shared__ float sbuf[32];
    int row = blockIdx.x;
    const float* xr = x + (size_t)row * TC;
    const float* rr = r + (size_t)row * TC;
    float* orow = out + (size_t)row * TC;
    int tid = threadIdx.x;

    float v[4];
    float s = 0.0f;
    #pragma unroll
    for (int i = 0; i < 4; i++) {
        int c = i * 256 + tid;
        v[i] = xr[c] + rr[c];
        s += v[i];
    }
    s = blk_reduce_sum(s, sbuf);
    float mean = s * (1.0f / (float)TC);
    float sq = 0.0f;
    #pragma unroll
    for (int i = 0; i < 4; i++) {
        float d = v[i] - mean;
        sq += d * d;
    }
    sq = blk_reduce_sum(sq, sbuf);
    float rstd = rsqrtf(sq * (1.0f / (float)TC) + 1e-5f);
    #pragma unroll
    for (int i = 0; i < 4; i++) {
        int c = i * 256 + tid;
        orow[c] = (v[i] - mean) * rstd * g[c] + be[c];
    }
}

// -------------------- launcher --------------------
extern "C" void kernel_launch(void* const* d_in, const int* in_sizes, int n_in,
                              void* d_out, int out_size)
{
    const float* x   = (const float*)d_in[0];
    const float* Wq  = (const float*)d_in[1];
    const float* bq  = (const float*)d_in[2];
    const float* Wk  = (const float*)d_in[3];
    const float* bk  = (const float*)d_in[4];
    const float* Wv  = (const float*)d_in[5];
    const float* bv  = (const float*)d_in[6];
    const float* g1  = (const float*)d_in[7];
    const float* be1 = (const float*)d_in[8];
    const float* W1  = (const float*)d_in[9];
    const float* bf1 = (const float*)d_in[10];
    const float* W2  = (const float*)d_in[11];
    const float* bf2 = (const float*)d_in[12];
    const float* g2  = (const float*)d_in[13];
    const float* be2 = (const float*)d_in[14];

    float *buf0, *buf1, *y1, *h1, *vsum, *wvs;
    cudaGetSymbolAddress((void**)&buf0, g_buf0);
    cudaGetSymbolAddress((void**)&buf1, g_buf1);
    cudaGetSymbolAddress((void**)&y1,   g_y1);
    cudaGetSymbolAddress((void**)&h1,   g_h1);
    cudaGetSymbolAddress((void**)&vsum, g_vsum);
    cudaGetSymbolAddress((void**)&wvs,  g_wvs);

    const int M = TM_TOTAL, N = TC, K = TC;
    dim3 gemm_grid(N / BN, M / BM);

    // v channel-sum collapses to a GEMV: vsum = x @ rowsum(Wv) + sum(bv)
    wvsum_kernel<<<TC + 1, 256>>>(Wv, bv, wvs);
    vsum_kernel<<<M, 256>>>(x, wvs, vsum);

    // q_t, k_t in [B,C,T]
    sgemm_kernel<1, 0><<<gemm_grid, 256>>>(x, Wq, bq, buf0, M, N, K);
    sgemm_kernel<1, 0><<<gemm_grid, 256>>>(x, Wk, bk, buf1, M, N, K);

    // FFT xcorr + softmax + *vsum -> attn_t (in-place over q_t)
    fft_corr_softmax<<<TB * TC, 256>>>(buf0, buf1, vsum, buf0);

    // attn_t [B,C,T] -> attn [B,T,C]
    transpose_kernel<<<dim3(TT / 32, TC / 32, TB), dim3(32, 8)>>>(buf0, buf1);

    // LN1: y1 = LN(x + attn)
    add_ln_kernel<<<M, 256>>>(x, buf1, g1, be1, y1);

    // FFN
    sgemm_kernel<0, 1><<<gemm_grid, 256>>>(y1, W1, bf1, h1, M, N, K);
    sgemm_kernel<0, 0><<<gemm_grid, 256>>>(h1, W2, bf2, buf0, M, N, K);

    // LN2 -> out
    add_ln_kernel<<<M, 256>>>(y1, buf0, g2, be2, (float*)d_out);
}

// round 3
// speedup vs baseline: 2.6328x; 2.6328x over previous
#include <cuda_runtime.h>
#include <cuda_bf16.h>
#include <math_constants.h>
#include <cstdint>

// Problem shape (fixed by the dataset)
#define TB 8
#define TT 2048
#define TC 1024
#define TM_TOTAL (TB*TT)      // 16384 rows

// ===================== scratch (no allocations allowed) =====================
__device__ float g_buf0[TB * TC * TT];          // q_t [B,C,T] -> attn_t -> h2 [B,T,C]
__device__ float g_buf1[TB * TC * TT];          // k_t [B,C,T] -> attn [B,T,C]
__device__ float g_y1  [TB * TT * TC];          // LN1 output fp32
__device__ float g_vsum[TB * TT];
__device__ float g_wvs [TC + 1];

// bf16 operand arrays in chunk-tiled, pre-swizzled layout:
//   A-type   [kc=16][m(16384)][64]  (tile = 128 m-rows x 128B, SW128-swizzled)
//   Wt-type  [kc=16][n(1024)][64]
__device__ __nv_bfloat16 g_xhi [TM_TOTAL * TC];
__device__ __nv_bfloat16 g_xlo [TM_TOTAL * TC];
__device__ __nv_bfloat16 g_y1hi[TM_TOTAL * TC];
__device__ __nv_bfloat16 g_y1lo[TM_TOTAL * TC];
__device__ __nv_bfloat16 g_h1hi[TM_TOTAL * TC];
__device__ __nv_bfloat16 g_h1lo[TM_TOTAL * TC];
__device__ __nv_bfloat16 g_wthi[4 * TC * TC];
__device__ __nv_bfloat16 g_wtlo[4 * TC * TC];

// ===================== PTX helpers =====================
__device__ __forceinline__ uint32_t smem_u32(const void* p) {
    uint32_t a;
    asm("{ .reg .u64 t; cvta.to.shared.u64 t, %1; cvt.u32.u64 %0, t; }" : "=r"(a) : "l"(p));
    return a;
}
#define SMEM_SWIZZLE_128B(o) ((o) ^ (((o) >> 3) & 0x70))

#define MBARRIER_INIT(mb, cnt) \
    asm volatile("mbarrier.init.shared.b64 [%0], %1;" :: "r"((uint32_t)(mb)), "r"((uint32_t)(cnt)) : "memory")
#define MBARRIER_INVAL(mb) \
    asm volatile("mbarrier.inval.shared.b64 [%0];" :: "r"((uint32_t)(mb)) : "memory")
#define MBARRIER_EXPECT_TX(mb, bytes) \
    asm volatile("mbarrier.arrive.expect_tx.shared.b64 _, [%0], %1;" :: "r"((uint32_t)(mb)), "r"((uint32_t)(bytes)) : "memory")
#define MBARRIER_WAIT_PARITY(mb, ph) do { \
    uint32_t _m = (uint32_t)(mb); uint32_t _p = (uint32_t)(ph); uint32_t _d; \
    asm volatile("{\n\t.reg .pred p;\n\tmbarrier.try_wait.parity.acquire.cta.shared::cta.b64 p, [%1], %2;\n\tselp.b32 %0, 1, 0, p;\n\t}" \
        : "=r"(_d) : "r"(_m), "r"(_p) : "memory"); \
    if (!_d) { \
        asm volatile("{\n\t.reg .pred P1;\n\tWL_%=:\n\tmbarrier.try_wait.parity.acquire.cta.shared::cta.b64 P1, [%0], %1, 0x989680;\n\t@P1 bra.uni WD_%=;\n\tbra.uni WL_%=;\n\tWD_%=:\n\t}" \
            :: "r"(_m), "r"(_p) : "memory"); \
    } } while (0)

#define BULK_G2S(dst, src, bytes, mbar) \
    asm volatile("cp.async.bulk.shared::cluster.global.mbarrier::complete_tx::bytes [%0], [%1], %2, [%3];" \
        :: "r"((uint32_t)(dst)), "l"(src), "r"((uint32_t)(bytes)), "r"((uint32_t)(mbar)) : "memory")

__device__ __forceinline__ void ldsm_x4(uint32_t* r, uint32_t addr) {
    asm volatile("ldmatrix.sync.aligned.m8n8.x4.shared.b16 {%0,%1,%2,%3}, [%4];"
                 : "=r"(r[0]), "=r"(r[1]), "=r"(r[2]), "=r"(r[3]) : "r"(addr));
}
__device__ __forceinline__ void ldsm_x2(uint32_t* r, uint32_t addr) {
    asm volatile("ldmatrix.sync.aligned.m8n8.x2.shared.b16 {%0,%1}, [%2];"
                 : "=r"(r[0]), "=r"(r[1]) : "r"(addr));
}
__device__ __forceinline__ void mma_bf16(float* d, const uint32_t* a, const uint32_t* b) {
    asm volatile("mma.sync.aligned.m16n8k16.row.col.f32.bf16.bf16.f32 "
                 "{%0,%1,%2,%3}, {%4,%5,%6,%7}, {%8,%9}, {%0,%1,%2,%3};"
                 : "+f"(d[0]), "+f"(d[1]), "+f"(d[2]), "+f"(d[3])
                 : "r"(a[0]), "r"(a[1]), "r"(a[2]), "r"(a[3]), "r"(b[0]), "r"(b[1]));
}

// position (elements) of element (row r, col k) in an A-type chunked array with R total rows
__device__ __forceinline__ size_t chunked_pos(int r, int k, int R) {
    uint32_t inb = SMEM_SWIZZLE_128B((uint32_t)((r & 127) * 128 + (k & 63) * 2));
    return (size_t)(k >> 6) * ((size_t)R * 64) + (size_t)(r & ~127) * 64 + (inb >> 1);
}

// ===================== block reductions (256 threads) =====================
__device__ __forceinline__ float blk_reduce_sum(float v, float* sbuf) {
    #pragma unroll
    for (int o = 16; o; o >>= 1) v += __shfl_xor_sync(0xffffffffu, v, o);
    if ((threadIdx.x & 31) == 0) sbuf[threadIdx.x >> 5] = v;
    __syncthreads();
    if (threadIdx.x < 32) {
        float w = (threadIdx.x < 8) ? sbuf[threadIdx.x] : 0.0f;
        #pragma unroll
        for (int o = 4; o; o >>= 1) w += __shfl_xor_sync(0xffffffffu, w, o);
        if (threadIdx.x == 0) sbuf[0] = w;
    }
    __syncthreads();
    float r = sbuf[0];
    __syncthreads();
    return r;
}
__device__ __forceinline__ float blk_reduce_max(float v, float* sbuf) {
    #pragma unroll
    for (int o = 16; o; o >>= 1) v = fmaxf(v, __shfl_xor_sync(0xffffffffu, v, o));
    if ((threadIdx.x & 31) == 0) sbuf[threadIdx.x >> 5] = v;
    __syncthreads();
    if (threadIdx.x < 32) {
        float w = (threadIdx.x < 8) ? sbuf[threadIdx.x] : -CUDART_INF_F;
        #pragma unroll
        for (int o = 4; o; o >>= 1) w = fmaxf(w, __shfl_xor_sync(0xffffffffu, w, o));
        if (threadIdx.x == 0) sbuf[0] = w;
    }
    __syncthreads();
    float r = sbuf[0];
    __syncthreads();
    return r;
}

// ===================== mma.sync GEMM =====================
// D[16384,1024] = A @ Wt^T + bias; A/Wt as bf16 hi/lo in chunked-swizzled layout.
// EPI: 0 = fp32 [M,N];  1 = fp32 transposed [B,C,T];  2 = relu + bf16 hi/lo (A-layout)
#define BM 128
#define BN 128
#define NCH 16
#define TSZ 16384                       // 128 rows x 128B
#define STAGE_BYTES (4*TSZ)             // 64KB
#define MB_OFF (2*STAGE_BYTES)
#define GEMM_SMEM (2*STAGE_BYTES + 64)

__device__ __forceinline__ void gemm_issue(
    const char* pAh, const char* pAl, const char* pBh, const char* pBl,
    int kc, uint32_t dst, uint32_t mb)
{
    MBARRIER_EXPECT_TX(mb, STAGE_BYTES);
    size_t aoff = (size_t)kc * ((size_t)TM_TOTAL * 128);
    size_t boff = (size_t)kc * ((size_t)TC * 128);
    BULK_G2S(dst,           pAh + aoff, TSZ, mb);
    BULK_G2S(dst + TSZ,     pAl + aoff, TSZ, mb);
    BULK_G2S(dst + 2*TSZ,   pBh + boff, TSZ, mb);
    BULK_G2S(dst + 3*TSZ,   pBl + boff, TSZ, mb);
}

template<int EPI>
__global__ void __launch_bounds__(256, 1)
gemm_tc(const __nv_bfloat16* __restrict__ Ah, const __nv_bfloat16* __restrict__ Al,
        const __nv_bfloat16* __restrict__ Bh, const __nv_bfloat16* __restrict__ Bl,
        const float* __restrict__ bias,
        float* out_f, __nv_bfloat16* out_hi, __nv_bfloat16* out_lo)
{
    extern __shared__ char smem[];
    const uint32_t sb = smem_u32(smem);
    const int tid = threadIdx.x;
    const int wid = tid >> 5;
    const int lane = tid & 31;
    const int wm = wid & 1;         // 2 warps in M (64 rows each)
    const int wn = wid >> 1;        // 4 warps in N (32 cols each)
    const int n0 = blockIdx.x * BN;
    const int m0 = blockIdx.y * BM;

    const char* pAh = (const char*)Ah + (size_t)m0 * 128;
    const char* pAl = (const char*)Al + (size_t)m0 * 128;
    const char* pBh = (const char*)Bh + (size_t)n0 * 128;
    const char* pBl = (const char*)Bl + (size_t)n0 * 128;

    if (tid == 0) { MBARRIER_INIT(sb + MB_OFF, 1); MBARRIER_INIT(sb + MB_OFF + 8, 1); }
    __syncthreads();

    if (tid == 0) {
        gemm_issue(pAh, pAl, pBh, pBl, 0, sb, sb + MB_OFF);
        gemm_issue(pAh, pAl, pBh, pBl, 1, sb + STAGE_BYTES, sb + MB_OFF + 8);
    }

    float acc[4][4][4];
    #pragma unroll
    for (int mi = 0; mi < 4; mi++)
        #pragma unroll
        for (int ni = 0; ni < 4; ni++)
            #pragma unroll
            for (int e = 0; e < 4; e++) acc[mi][ni][e] = 0.0f;

    int ph[2] = {0, 0};
    #pragma unroll 1
    for (int kc = 0; kc < NCH; kc++) {
        const int s = kc & 1;
        MBARRIER_WAIT_PARITY(sb + MB_OFF + 8*s, ph[s]); ph[s] ^= 1;
        const uint32_t st = sb + s * STAGE_BYTES;

        #pragma unroll
        for (int ks = 0; ks < 4; ks++) {
            uint32_t ah[4][4], al[4][4], bh[4][2], bl[4][2];
            const int arow = wm * 64 + (lane & 15);
            const int aoffb = ks * 32 + ((lane >> 4) << 4);
            #pragma unroll
            for (int mi = 0; mi < 4; mi++) {
                uint32_t o = SMEM_SWIZZLE_128B((uint32_t)((arow + mi*16) * 128 + aoffb));
                ldsm_x4(ah[mi], st + o);
                ldsm_x4(al[mi], st + TSZ + o);
            }
            const int brow = wn * 32 + (lane & 7);
            const int boffb = ks * 32 + ((lane >> 3) & 1) * 16;
            #pragma unroll
            for (int ni = 0; ni < 4; ni++) {
                uint32_t o = SMEM_SWIZZLE_128B((uint32_t)((brow + ni*8) * 128 + boffb));
                ldsm_x2(bh[ni], st + 2*TSZ + o);
                ldsm_x2(bl[ni], st + 3*TSZ + o);
            }
            #pragma unroll
            for (int mi = 0; mi < 4; mi++)
                #pragma unroll
                for (int ni = 0; ni < 4; ni++) {
                    mma_bf16(acc[mi][ni], ah[mi], bh[ni]);
                    mma_bf16(acc[mi][ni], ah[mi], bl[ni]);
                    mma_bf16(acc[mi][ni], al[mi], bh[ni]);
                }
        }
        __syncthreads();
        if (kc + 2 < NCH && tid == 0)
            gemm_issue(pAh, pAl, pBh, pBl, kc + 2, st, sb + MB_OFF + 8*s);
    }

    // stage accumulators through padded smem (stride 133 -> conflict-free columns)
    float* stile = (float*)smem;
    {
        const int rg = lane >> 2;
        const int cg = (lane & 3) * 2;
        #pragma unroll
        for (int mi = 0; mi < 4; mi++)
            #pragma unroll
            for (int ni = 0; ni < 4; ni++) {
                int r = wm*64 + mi*16 + rg;
                int c = wn*32 + ni*8 + cg;
                stile[r*133 + c]       = acc[mi][ni][0];
                stile[r*133 + c + 1]   = acc[mi][ni][1];
                stile[(r+8)*133 + c]     = acc[mi][ni][2];
                stile[(r+8)*133 + c + 1] = acc[mi][ni][3];
            }
    }
    __syncthreads();

    if (EPI == 0) {
        for (int idx = tid; idx < BM*BN; idx += 256) {
            int r = idx >> 7, c = idx & 127;
            out_f[(size_t)(m0 + r) * TC + n0 + c] = stile[r*133 + c] + __ldg(bias + n0 + c);
        }
    } else if (EPI == 1) {
        const int b = m0 >> 11, t0 = m0 & (TT - 1);
        for (int idx = tid; idx < BM*BN; idx += 256) {
            int n = idx >> 7, cm = idx & 127;
            float v = stile[cm*133 + n] + __ldg(bias + n0 + n);
            out_f[((size_t)(b * TC + n0 + n)) * TT + t0 + cm] = v;
        }
    } else {
        for (int idx = tid; idx < BM*BN; idx += 256) {
            int r = idx >> 7, c = idx & 127;
            float v = fmaxf(stile[r*133 + c] + __ldg(bias + n0 + c), 0.0f);
            __nv_bfloat16 h = __float2bfloat16(v);
            __nv_bfloat16 l = __float2bfloat16(v - __bfloat162float(h));
            size_t pos = chunked_pos(m0 + r, n0 + c, TM_TOTAL);
            out_hi[pos] = h;
            out_lo[pos] = l;
        }
    }
}

// ===================== fp32 [M,C] -> bf16 hi/lo in chunked A-layout =====================
__global__ void split_kernel(const float* __restrict__ x,
                             __nv_bfloat16* __restrict__ hi, __nv_bfloat16* __restrict__ lo)
{
    const size_t i = ((size_t)blockIdx.x * 256 + threadIdx.x) * 4;
    const int m = (int)(i >> 10);
    const int c = (int)(i & 1023);
    float4 v = *(const float4*)(x + i);
    __nv_bfloat16 h0 = __float2bfloat16(v.x), h1 = __float2bfloat16(v.y);
    __nv_bfloat16 h2 = __float2bfloat16(v.z), h3 = __float2bfloat16(v.w);
    __nv_bfloat162 hh0(h0, h1), hh1(h2, h3);
    __nv_bfloat162 ll0(__float2bfloat16(v.x - __bfloat162float(h0)), __float2bfloat16(v.y - __bfloat162float(h1)));
    __nv_bfloat162 ll1(__float2bfloat16(v.z - __bfloat162float(h2)), __float2bfloat16(v.w - __bfloat162float(h3)));
    size_t pos = chunked_pos(m, c, TM_TOTAL);   // 4 consecutive elems stay contiguous (8B within 16B unit)
    *(__nv_bfloat162*)(hi + pos)     = hh0;
    *(__nv_bfloat162*)(hi + pos + 2) = hh1;
    *(__nv_bfloat162*)(lo + pos)     = ll0;
    *(__nv_bfloat162*)(lo + pos + 2) = ll1;
}

// ===================== W[K,N] -> Wt[N,K] bf16 hi/lo, chunked layout =====================
__global__ void transpose_split_w(const float* __restrict__ W,
                                  __nv_bfloat16* __restrict__ hi, __nv_bfloat16* __restrict__ lo)
{
    __shared__ float tile[32][33];
    const int n0 = blockIdx.x * 32;
    const int k0 = blockIdx.y * 32;
    #pragma unroll
    for (int y = threadIdx.y; y < 32; y += 8)
        tile[y][threadIdx.x] = W[(size_t)(k0 + y) * TC + n0 + threadIdx.x];
    __syncthreads();
    #pragma unroll
    for (int y = threadIdx.y; y < 32; y += 8) {
        float v = tile[threadIdx.x][y];
        __nv_bfloat16 h = __float2bfloat16(v);
        size_t pos = chunked_pos(n0 + y, k0 + threadIdx.x, TC);
        hi[pos] = h;
        lo[pos] = __float2bfloat16(v - __bfloat162float(h));
    }
}

// ===================== wvsum / vsum =====================
__global__ void wvsum_kernel(const float* __restrict__ Wv, const float* __restrict__ bv,
                             float* __restrict__ out)
{
    __shared__ float sbuf[32];
    int d = blockIdx.x;
    const float* src = (d < TC) ? (Wv + (size_t)d * TC) : bv;
    float s = 0.0f;
    for (int c = threadIdx.x; c < TC; c += 256) s += src[c];
    s = blk_reduce_sum(s, sbuf);
    if (threadIdx.x == 0) out[d] = s;
}
__global__ void vsum_kernel(const float* __restrict__ x, const float* __restrict__ wvs,
                            float* __restrict__ out)
{
    __shared__ float sbuf[32];
    int row = blockIdx.x;
    const float* xr = x + (size_t)row * TC;
    float s = 0.0f;
    for (int c = threadIdx.x; c < TC; c += 256) s += xr[c] * wvs[c];
    s = blk_reduce_sum(s, sbuf);
    if (threadIdx.x == 0) out[row] = s + wvs[TC];
}

// ===================== FFT correlation + softmax + *vsum =====================
__device__ __forceinline__ void fft_stages(float2* z, const float2* tw, int tid, bool inverse)
{
    #pragma unroll
    for (int s = 1; s <= 11; s++) {
        int half = 1 << (s - 1);
        int tshift = 11 - s;
        for (int j = tid; j < 1024; j += 256) {
            int grp = j >> (s - 1);
            int pos = j & (half - 1);
            int i1 = (grp << s) + pos;
            int i2 = i1 + half;
            float2 w = tw[pos << tshift];
            if (inverse) w.y = -w.y;
            float2 u = z[i1];
            float2 v = z[i2];
            float tr = w.x * v.x - w.y * v.y;
            float ti = w.x * v.y + w.y * v.x;
            z[i1] = make_float2(u.x + tr, u.y + ti);
            z[i2] = make_float2(u.x - tr, u.y - ti);
        }
        __syncthreads();
    }
}

__global__ void __launch_bounds__(256)
fft_corr_softmax(const float* qt, const float* kt,
                 const float* __restrict__ vsum, float* attn_t)
{
    __shared__ float2 z[2048];
    __shared__ float2 tw[1024];
    __shared__ float sbuf[32];

    const int bc = blockIdx.x;
    const int b = bc >> 10;
    const int tid = threadIdx.x;
    const float* qrow = qt + (size_t)bc * TT;
    const float* krow = kt + (size_t)bc * TT;

    for (int j = tid; j < 1024; j += 256) {
        float sv, cv;
        sincosf(-6.283185307179586f * ((float)j * (1.0f / 2048.0f)), &sv, &cv);
        tw[j] = make_float2(cv, sv);
    }
    for (int t = tid; t < 2048; t += 256) {
        int r = __brev((unsigned)t) >> 21;
        z[r] = make_float2(qrow[t], krow[t]);
    }
    __syncthreads();

    fft_stages(z, tw, tid, false);

    for (int f = tid; f <= 1024; f += 256) {
        int g = (2048 - f) & 2047;
        float2 zf = z[f], zg = z[g];
        float Qr = 0.5f * (zf.x + zg.x);
        float Qi = 0.5f * (zf.y - zg.y);
        float Kr = 0.5f * (zf.y + zg.y);
        float Ki = 0.5f * (zg.x - zf.x);
        float Pr = Qr * Kr + Qi * Ki;
        float Pi = Qi * Kr - Qr * Ki;
        z[f] = make_float2(Pr, Pi);
        z[g] = make_float2(Pr, -Pi);
    }
    __syncthreads();

    for (int t = tid; t < 2048; t += 256) {
        int r = __brev((unsigned)t) >> 21;
        if (r > t) { float2 a = z[t]; z[t] = z[r]; z[r] = a; }
    }
    __syncthreads();
    fft_stages(z, tw, tid, true);

    float cvals[8];
    float vmax = -CUDART_INF_F;
    #pragma unroll
    for (int i = 0; i < 8; i++) {
        int t = tid + i * 256;
        cvals[i] = z[t].x * (1.0f / 2048.0f);
        vmax = fmaxf(vmax, cvals[i]);
    }
    vmax = blk_reduce_max(vmax, sbuf);
    float ssum = 0.0f;
    #pragma unroll
    for (int i = 0; i < 8; i++) {
        cvals[i] = expf(cvals[i] - vmax);
        ssum += cvals[i];
    }
    ssum = blk_reduce_sum(ssum, sbuf);
    float inv = 1.0f / ssum;

    const float* vs = vsum + (size_t)b * TT;
    float* arow = attn_t + (size_t)bc * TT;
    #pragma unroll
    for (int i = 0; i < 8; i++) {
        int t = tid + i * 256;
        arow[t] = cvals[i] * inv * vs[t];
    }
}

// ===================== transpose [B,C,T] -> [B,T,C] =====================
__global__ void transpose_kernel(const float* __restrict__ in, float* __restrict__ out)
{
    __shared__ float tile[32][33];
    int b = blockIdx.z;
    int t0 = blockIdx.x * 32;
    int c0 = blockIdx.y * 32;
    const float* inb = in + (size_t)b * TC * TT;
    float* outb = out + (size_t)b * TT * TC;
    #pragma unroll
    for (int y = threadIdx.y; y < 32; y += 8)
        tile[y][threadIdx.x] = inb[(size_t)(c0 + y) * TT + t0 + threadIdx.x];
    __syncthreads();
    #pragma unroll
    for (int y = threadIdx.y; y < 32; y += 8)
        outb[(size_t)(t0 + y) * TC + c0 + threadIdx.x] = tile[threadIdx.x][y];
}

// ===================== residual + layernorm (opt chunked split output) =====================
template<int SPLIT>
__global__ void __launch_bounds__(256)
add_ln_kernel(const float* __restrict__ x, const float* __restrict__ r,
              const float* __restrict__ g, const float* __restrict__ be,
              float* __restrict__ out,
              __nv_bfloat16* __restrict__ ohi, __nv_bfloat16* __restrict__ olo)
{
    __shared__ float sbuf[32];
    int row = blockIdx.x;
    const float* xr = x + (size_t)row * TC;
    const float* rr = r + (size_t)row * TC;
    int tid = threadIdx.x;

    float v[4];
    float s = 0.0f;
    #pragma unroll
    for (int i = 0; i < 4; i++) {
        int c = i * 256 + tid;
        v[i] = xr[c] + rr[c];
        s += v[i];
    }
    s = blk_reduce_sum(s, sbuf);
    float mean = s * (1.0f / (float)TC);
    float sq = 0.0f;
    #pragma unroll
    for (int i = 0; i < 4; i++) {
        float d = v[i] - mean;
        sq += d * d;
    }
    sq = blk_reduce_sum(sq, sbuf);
    float rstd = rsqrtf(sq * (1.0f / (float)TC) + 1e-5f);
    #pragma unroll
    for (int i = 0; i < 4; i++) {
        int c = i * 256 + tid;
        float y = (v[i] - mean) * rstd * g[c] + be[c];
        out[(size_t)row * TC + c] = y;
        if (SPLIT) {
            __nv_bfloat16 h = __float2bfloat16(y);
            size_t pos = chunked_pos(row, c, TM_TOTAL);
            ohi[pos] = h;
            olo[pos] = __float2bfloat16(y - __bfloat162float(h));
        }
    }
}

// ===================== launcher =====================
extern "C" void kernel_launch(void* const* d_in, const int* in_sizes, int n_in,
                              void* d_out, int out_size)
{
    const float* x   = (const float*)d_in[0];
    const float* Wq  = (const float*)d_in[1];
    const float* bq  = (const float*)d_in[2];
    const float* Wk  = (const float*)d_in[3];
    const float* bk  = (const float*)d_in[4];
    const float* Wv  = (const float*)d_in[5];
    const float* bv  = (const float*)d_in[6];
    const float* g1  = (const float*)d_in[7];
    const float* be1 = (const float*)d_in[8];
    const float* W1  = (const float*)d_in[9];
    const float* bf1 = (const float*)d_in[10];
    const float* W2  = (const float*)d_in[11];
    const float* bf2 = (const float*)d_in[12];
    const float* g2  = (const float*)d_in[13];
    const float* be2 = (const float*)d_in[14];

    float *buf0, *buf1, *y1, *vsum, *wvs;
    __nv_bfloat16 *xhi, *xlo, *y1hi, *y1lo, *h1hi, *h1lo, *wthi, *wtlo;
    cudaGetSymbolAddress((void**)&buf0, g_buf0);
    cudaGetSymbolAddress((void**)&buf1, g_buf1);
    cudaGetSymbolAddress((void**)&y1,   g_y1);
    cudaGetSymbolAddress((void**)&vsum, g_vsum);
    cudaGetSymbolAddress((void**)&wvs,  g_wvs);
    cudaGetSymbolAddress((void**)&xhi,  g_xhi);
    cudaGetSymbolAddress((void**)&xlo,  g_xlo);
    cudaGetSymbolAddress((void**)&y1hi, g_y1hi);
    cudaGetSymbolAddress((void**)&y1lo, g_y1lo);
    cudaGetSymbolAddress((void**)&h1hi, g_h1hi);
    cudaGetSymbolAddress((void**)&h1lo, g_h1lo);
    cudaGetSymbolAddress((void**)&wthi, g_wthi);
    cudaGetSymbolAddress((void**)&wtlo, g_wtlo);

    cudaFuncSetAttribute(gemm_tc<0>, cudaFuncAttributeMaxDynamicSharedMemorySize, GEMM_SMEM);
    cudaFuncSetAttribute(gemm_tc<1>, cudaFuncAttributeMaxDynamicSharedMemorySize, GEMM_SMEM);
    cudaFuncSetAttribute(gemm_tc<2>, cudaFuncAttributeMaxDynamicSharedMemorySize, GEMM_SMEM);

    const int M = TM_TOTAL;
    const size_t WSTRIDE = (size_t)TC * TC;
    dim3 wgrid(32, 32), wblk(32, 8);
    dim3 ggrid(TC / BN, M / BM);   // (8, 128)

    // prep: split x, transpose+split weights (into chunked-swizzled layouts)
    split_kernel<<<(M * TC) / (256 * 4), 256>>>(x, xhi, xlo);
    transpose_split_w<<<wgrid, wblk>>>(Wq, wthi + 0*WSTRIDE, wtlo + 0*WSTRIDE);
    transpose_split_w<<<wgrid, wblk>>>(Wk, wthi + 1*WSTRIDE, wtlo + 1*WSTRIDE);
    transpose_split_w<<<wgrid, wblk>>>(W1, wthi + 2*WSTRIDE, wtlo + 2*WSTRIDE);
    transpose_split_w<<<wgrid, wblk>>>(W2, wthi + 3*WSTRIDE, wtlo + 3*WSTRIDE);

    // v channel-sum collapses to a GEMV
    wvsum_kernel<<<TC + 1, 256>>>(Wv, bv, wvs);
    vsum_kernel<<<M, 256>>>(x, wvs, vsum);

    // q_t, k_t in [B,C,T] via tensor-core GEMM with transposed epilogue
    gemm_tc<1><<<ggrid, 256, GEMM_SMEM>>>(xhi, xlo, wthi + 0*WSTRIDE, wtlo + 0*WSTRIDE, bq, buf0, nullptr, nullptr);
    gemm_tc<1><<<ggrid, 256, GEMM_SMEM>>>(xhi, xlo, wthi + 1*WSTRIDE, wtlo + 1*WSTRIDE, bk, buf1, nullptr, nullptr);

    // FFT xcorr + softmax + *vsum
    fft_corr_softmax<<<TB * TC, 256>>>(buf0, buf1, vsum, buf0);

    // attn_t [B,C,T] -> attn [B,T,C]
    transpose_kernel<<<dim3(TT / 32, TC / 32, TB), dim3(32, 8)>>>(buf0, buf1);

    // LN1 (emits fp32 + chunked bf16 hi/lo)
    add_ln_kernel<1><<<M, 256>>>(x, buf1, g1, be1, y1, y1hi, y1lo);

    // FFN
    gemm_tc<2><<<ggrid, 256, GEMM_SMEM>>>(y1hi, y1lo, wthi + 2*WSTRIDE, wtlo + 2*WSTRIDE, bf1, nullptr, h1hi, h1lo);
    gemm_tc<0><<<ggrid, 256, GEMM_SMEM>>>(h1hi, h1lo, wthi + 3*WSTRIDE, wtlo + 3*WSTRIDE, bf2, buf0, nullptr, nullptr);

    // LN2 -> out
    add_ln_kernel<0><<<M, 256>>>(y1, buf0, g2, be2, (float*)d_out, nullptr, nullptr);
}

// round 4
// speedup vs baseline: 2.9327x; 1.1139x over previous
#include <cuda_runtime.h>
#include <cuda_bf16.h>
#include <math_constants.h>
#include <cstdint>

// Problem shape (fixed by the dataset)
#define TB 8
#define TT 2048
#define TC 1024
#define TM_TOTAL (TB*TT)      // 16384 rows

// ===================== scratch (no allocations allowed) =====================
__device__ float g_buf0[TB * TC * TT];          // q_t [B,C,T] -> attn_t -> h2 [B,T,C]
__device__ float g_buf1[TB * TC * TT];          // k_t [B,C,T] -> attn [B,T,C]
__device__ float g_y1  [TB * TT * TC];          // LN1 output fp32
__device__ float g_vsum[TB * TT];
__device__ float g_wvs [TC + 1];
__device__ float2 g_tw [1024];                  // e^{-2pi i j/2048}

// bf16 operand arrays in chunk-tiled, pre-swizzled layout:
//   A-type   [kc=16][m(16384)][64]  (tile = 128 m-rows x 128B, SW128-swizzled)
//   Wt-type  [kc=16][n(1024)][64]
__device__ __nv_bfloat16 g_xhi [TM_TOTAL * TC];
__device__ __nv_bfloat16 g_xlo [TM_TOTAL * TC];
__device__ __nv_bfloat16 g_y1hi[TM_TOTAL * TC];
__device__ __nv_bfloat16 g_y1lo[TM_TOTAL * TC];
__device__ __nv_bfloat16 g_h1hi[TM_TOTAL * TC];
__device__ __nv_bfloat16 g_h1lo[TM_TOTAL * TC];
__device__ __nv_bfloat16 g_wthi[4 * TC * TC];
__device__ __nv_bfloat16 g_wtlo[4 * TC * TC];

// ===================== PTX helpers =====================
__device__ __forceinline__ uint32_t smem_u32(const void* p) {
    uint32_t a;
    asm("{ .reg .u64 t; cvta.to.shared.u64 t, %1; cvt.u32.u64 %0, t; }" : "=r"(a) : "l"(p));
    return a;
}
#define SMEM_SWIZZLE_128B(o) ((o) ^ (((o) >> 3) & 0x70))

#define MBARRIER_INIT(mb, cnt) \
    asm volatile("mbarrier.init.shared.b64 [%0], %1;" :: "r"((uint32_t)(mb)), "r"((uint32_t)(cnt)) : "memory")
#define MBARRIER_EXPECT_TX(mb, bytes) \
    asm volatile("mbarrier.arrive.expect_tx.shared.b64 _, [%0], %1;" :: "r"((uint32_t)(mb)), "r"((uint32_t)(bytes)) : "memory")
#define MBARRIER_WAIT_PARITY(mb, ph) do { \
    uint32_t _m = (uint32_t)(mb); uint32_t _p = (uint32_t)(ph); uint32_t _d; \
    asm volatile("{\n\t.reg .pred p;\n\tmbarrier.try_wait.parity.acquire.cta.shared::cta.b64 p, [%1], %2;\n\tselp.b32 %0, 1, 0, p;\n\t}" \
        : "=r"(_d) : "r"(_m), "r"(_p) : "memory"); \
    if (!_d) { \
        asm volatile("{\n\t.reg .pred P1;\n\tWL_%=:\n\tmbarrier.try_wait.parity.acquire.cta.shared::cta.b64 P1, [%0], %1, 0x989680;\n\t@P1 bra.uni WD_%=;\n\tbra.uni WL_%=;\n\tWD_%=:\n\t}" \
            :: "r"(_m), "r"(_p) : "memory"); \
    } } while (0)

#define BULK_G2S(dst, src, bytes, mbar) \
    asm volatile("cp.async.bulk.shared::cluster.global.mbarrier::complete_tx::bytes [%0], [%1], %2, [%3];" \
        :: "r"((uint32_t)(dst)), "l"(src), "r"((uint32_t)(bytes)), "r"((uint32_t)(mbar)) : "memory")

__device__ __forceinline__ void ldsm_x4(uint32_t* r, uint32_t addr) {
    asm volatile("ldmatrix.sync.aligned.m8n8.x4.shared.b16 {%0,%1,%2,%3}, [%4];"
                 : "=r"(r[0]), "=r"(r[1]), "=r"(r[2]), "=r"(r[3]) : "r"(addr));
}
__device__ __forceinline__ void ldsm_x2(uint32_t* r, uint32_t addr) {
    asm volatile("ldmatrix.sync.aligned.m8n8.x2.shared.b16 {%0,%1}, [%2];"
                 : "=r"(r[0]), "=r"(r[1]) : "r"(addr));
}
__device__ __forceinline__ void mma_bf16(float* d, const uint32_t* a, const uint32_t* b) {
    asm volatile("mma.sync.aligned.m16n8k16.row.col.f32.bf16.bf16.f32 "
                 "{%0,%1,%2,%3}, {%4,%5,%6,%7}, {%8,%9}, {%0,%1,%2,%3};"
                 : "+f"(d[0]), "+f"(d[1]), "+f"(d[2]), "+f"(d[3])
                 : "r"(a[0]), "r"(a[1]), "r"(a[2]), "r"(a[3]), "r"(b[0]), "r"(b[1]));
}

// position (elements) of element (row r, col k) in an A-type chunked array with R total rows
__device__ __forceinline__ size_t chunked_pos(int r, int k, int R) {
    uint32_t inb = SMEM_SWIZZLE_128B((uint32_t)((r & 127) * 128 + (k & 63) * 2));
    return (size_t)(k >> 6) * ((size_t)R * 64) + (size_t)(r & ~127) * 64 + (inb >> 1);
}

// ===================== block reductions (256 threads) =====================
__device__ __forceinline__ float blk_reduce_sum(float v, float* sbuf) {
    #pragma unroll
    for (int o = 16; o; o >>= 1) v += __shfl_xor_sync(0xffffffffu, v, o);
    if ((threadIdx.x & 31) == 0) sbuf[threadIdx.x >> 5] = v;
    __syncthreads();
    if (threadIdx.x < 32) {
        float w = (threadIdx.x < 8) ? sbuf[threadIdx.x] : 0.0f;
        #pragma unroll
        for (int o = 4; o; o >>= 1) w += __shfl_xor_sync(0xffffffffu, w, o);
        if (threadIdx.x == 0) sbuf[0] = w;
    }
    __syncthreads();
    float r = sbuf[0];
    __syncthreads();
    return r;
}
__device__ __forceinline__ float blk_reduce_max(float v, float* sbuf) {
    #pragma unroll
    for (int o = 16; o; o >>= 1) v = fmaxf(v, __shfl_xor_sync(0xffffffffu, v, o));
    if ((threadIdx.x & 31) == 0) sbuf[threadIdx.x >> 5] = v;
    __syncthreads();
    if (threadIdx.x < 32) {
        float w = (threadIdx.x < 8) ? sbuf[threadIdx.x] : -CUDART_INF_F;
        #pragma unroll
        for (int o = 4; o; o >>= 1) w = fmaxf(w, __shfl_xor_sync(0xffffffffu, w, o));
        if (threadIdx.x == 0) sbuf[0] = w;
    }
    __syncthreads();
    float r = sbuf[0];
    __syncthreads();
    return r;
}

// ===================== mma.sync GEMM (3-stage bulk-copy pipeline) =====================
// D[16384,1024] = A @ Wt^T + bias; A/Wt as bf16 hi/lo in chunked-swizzled layout.
// EPI: 0 = fp32 [M,N];  1 = fp32 transposed [B,C,T];  2 = relu + bf16 hi/lo (A-layout)
#define BM 128
#define BN 128
#define NCH 16
#define NST 3
#define TSZ 16384                       // 128 rows x 128B
#define STAGE_BYTES (4*TSZ)             // 64KB
#define MB_OFF (NST*STAGE_BYTES)
#define GEMM_SMEM (NST*STAGE_BYTES + 64)

__device__ __forceinline__ void gemm_issue(
    const char* pAh, const char* pAl, const char* pBh, const char* pBl,
    int kc, uint32_t dst, uint32_t mb)
{
    MBARRIER_EXPECT_TX(mb, STAGE_BYTES);
    size_t aoff = (size_t)kc * ((size_t)TM_TOTAL * 128);
    size_t boff = (size_t)kc * ((size_t)TC * 128);
    BULK_G2S(dst,           pAh + aoff, TSZ, mb);
    BULK_G2S(dst + TSZ,     pAl + aoff, TSZ, mb);
    BULK_G2S(dst + 2*TSZ,   pBh + boff, TSZ, mb);
    BULK_G2S(dst + 3*TSZ,   pBl + boff, TSZ, mb);
}

template<int EPI>
__global__ void __launch_bounds__(256, 1)
gemm_tc(const __nv_bfloat16* __restrict__ Ah, const __nv_bfloat16* __restrict__ Al,
        const __nv_bfloat16* __restrict__ Bh, const __nv_bfloat16* __restrict__ Bl,
        const float* __restrict__ bias,
        float* out_f, __nv_bfloat16* out_hi, __nv_bfloat16* out_lo)
{
    extern __shared__ char smem[];
    const uint32_t sb = smem_u32(smem);
    const int tid = threadIdx.x;
    const int wid = tid >> 5;
    const int lane = tid & 31;
    const int wm = wid & 1;         // 2 warps in M (64 rows each)
    const int wn = wid >> 1;        // 4 warps in N (32 cols each)
    const int n0 = blockIdx.x * BN;
    const int m0 = blockIdx.y * BM;

    const char* pAh = (const char*)Ah + (size_t)m0 * 128;
    const char* pAl = (const char*)Al + (size_t)m0 * 128;
    const char* pBh = (const char*)Bh + (size_t)n0 * 128;
    const char* pBl = (const char*)Bl + (size_t)n0 * 128;

    if (tid == 0) {
        #pragma unroll
        for (int s = 0; s < NST; s++) MBARRIER_INIT(sb + MB_OFF + 8*s, 1);
    }
    __syncthreads();

    if (tid == 0) {
        #pragma unroll
        for (int s = 0; s < NST; s++)
            gemm_issue(pAh, pAl, pBh, pBl, s, sb + s*STAGE_BYTES, sb + MB_OFF + 8*s);
    }

    float acc[4][4][4];
    #pragma unroll
    for (int mi = 0; mi < 4; mi++)
        #pragma unroll
        for (int ni = 0; ni < 4; ni++)
            #pragma unroll
            for (int e = 0; e < 4; e++) acc[mi][ni][e] = 0.0f;

    int ph[NST] = {0, 0, 0};
    int s = 0;
    #pragma unroll 1
    for (int kc = 0; kc < NCH; kc++) {
        MBARRIER_WAIT_PARITY(sb + MB_OFF + 8*s, ph[s]); ph[s] ^= 1;
        const uint32_t st = sb + s * STAGE_BYTES;

        #pragma unroll
        for (int ks = 0; ks < 4; ks++) {
            uint32_t ah[4][4], al[4][4], bh[4][2], bl[4][2];
            const int arow = wm * 64 + (lane & 15);
            const int aoffb = ks * 32 + ((lane >> 4) << 4);
            #pragma unroll
            for (int mi = 0; mi < 4; mi++) {
                uint32_t o = SMEM_SWIZZLE_128B((uint32_t)((arow + mi*16) * 128 + aoffb));
                ldsm_x4(ah[mi], st + o);
                ldsm_x4(al[mi], st + TSZ + o);
            }
            const int brow = wn * 32 + (lane & 7);
            const int boffb = ks * 32 + ((lane >> 3) & 1) * 16;
            #pragma unroll
            for (int ni = 0; ni < 4; ni++) {
                uint32_t o = SMEM_SWIZZLE_128B((uint32_t)((brow + ni*8) * 128 + boffb));
                ldsm_x2(bh[ni], st + 2*TSZ + o);
                ldsm_x2(bl[ni], st + 3*TSZ + o);
            }
            #pragma unroll
            for (int mi = 0; mi < 4; mi++)
                #pragma unroll
                for (int ni = 0; ni < 4; ni++) {
                    mma_bf16(acc[mi][ni], ah[mi], bh[ni]);
                    mma_bf16(acc[mi][ni], ah[mi], bl[ni]);
                    mma_bf16(acc[mi][ni], al[mi], bh[ni]);
                }
        }
        __syncthreads();
        if (kc + NST < NCH && tid == 0)
            gemm_issue(pAh, pAl, pBh, pBl, kc + NST, st, sb + MB_OFF + 8*s);
        s = (s == NST-1) ? 0 : s + 1;
    }

    // stage accumulators through padded smem (stride 133 -> conflict-free columns)
    float* stile = (float*)smem;
    {
        const int rg = lane >> 2;
        const int cg = (lane & 3) * 2;
        #pragma unroll
        for (int mi = 0; mi < 4; mi++)
            #pragma unroll
            for (int ni = 0; ni < 4; ni++) {
                int r = wm*64 + mi*16 + rg;
                int c = wn*32 + ni*8 + cg;
                stile[r*133 + c]       = acc[mi][ni][0];
                stile[r*133 + c + 1]   = acc[mi][ni][1];
                stile[(r+8)*133 + c]     = acc[mi][ni][2];
                stile[(r+8)*133 + c + 1] = acc[mi][ni][3];
            }
    }
    __syncthreads();

    if (EPI == 0) {
        for (int idx = tid; idx < BM*BN; idx += 256) {
            int r = idx >> 7, c = idx & 127;
            out_f[(size_t)(m0 + r) * TC + n0 + c] = stile[r*133 + c] + __ldg(bias + n0 + c);
        }
    } else if (EPI == 1) {
        const int b = m0 >> 11, t0 = m0 & (TT - 1);
        for (int idx = tid; idx < BM*BN; idx += 256) {
            int n = idx >> 7, cm = idx & 127;
            float v = stile[cm*133 + n] + __ldg(bias + n0 + n);
            out_f[((size_t)(b * TC + n0 + n)) * TT + t0 + cm] = v;
        }
    } else {
        for (int idx = tid; idx < BM*BN; idx += 256) {
            int r = idx >> 7, c = idx & 127;
            float v = fmaxf(stile[r*133 + c] + __ldg(bias + n0 + c), 0.0f);
            __nv_bfloat16 h = __float2bfloat16(v);
            __nv_bfloat16 l = __float2bfloat16(v - __bfloat162float(h));
            size_t pos = chunked_pos(m0 + r, n0 + c, TM_TOTAL);
            out_hi[pos] = h;
            out_lo[pos] = l;
        }
    }
}

// ===================== fp32 [M,C] -> bf16 hi/lo in chunked A-layout =====================
__global__ void split_kernel(const float* __restrict__ x,
                             __nv_bfloat16* __restrict__ hi, __nv_bfloat16* __restrict__ lo)
{
    const size_t i = ((size_t)blockIdx.x * 256 + threadIdx.x) * 4;
    const int m = (int)(i >> 10);
    const int c = (int)(i & 1023);
    float4 v = *(const float4*)(x + i);
    __nv_bfloat16 h0 = __float2bfloat16(v.x), h1 = __float2bfloat16(v.y);
    __nv_bfloat16 h2 = __float2bfloat16(v.z), h3 = __float2bfloat16(v.w);
    __nv_bfloat162 hh0(h0, h1), hh1(h2, h3);
    __nv_bfloat162 ll0(__float2bfloat16(v.x - __bfloat162float(h0)), __float2bfloat16(v.y - __bfloat162float(h1)));
    __nv_bfloat162 ll1(__float2bfloat16(v.z - __bfloat162float(h2)), __float2bfloat16(v.w - __bfloat162float(h3)));
    size_t pos = chunked_pos(m, c, TM_TOTAL);
    *(__nv_bfloat162*)(hi + pos)     = hh0;
    *(__nv_bfloat162*)(hi + pos + 2) = hh1;
    *(__nv_bfloat162*)(lo + pos)     = ll0;
    *(__nv_bfloat162*)(lo + pos + 2) = ll1;
}

// ===================== W[K,N] -> Wt[N,K] bf16 hi/lo, chunked layout =====================
__global__ void transpose_split_w(const float* __restrict__ W,
                                  __nv_bfloat16* __restrict__ hi, __nv_bfloat16* __restrict__ lo)
{
    __shared__ float tile[32][33];
    const int n0 = blockIdx.x * 32;
    const int k0 = blockIdx.y * 32;
    #pragma unroll
    for (int y = threadIdx.y; y < 32; y += 8)
        tile[y][threadIdx.x] = W[(size_t)(k0 + y) * TC + n0 + threadIdx.x];
    __syncthreads();
    #pragma unroll
    for (int y = threadIdx.y; y < 32; y += 8) {
        float v = tile[threadIdx.x][y];
        __nv_bfloat16 h = __float2bfloat16(v);
        size_t pos = chunked_pos(n0 + y, k0 + threadIdx.x, TC);
        hi[pos] = h;
        lo[pos] = __float2bfloat16(v - __bfloat162float(h));
    }
}

// ===================== wvsum / vsum / twiddles =====================
__global__ void wvsum_kernel(const float* __restrict__ Wv, const float* __restrict__ bv,
                             float* __restrict__ out)
{
    __shared__ float sbuf[32];
    int d = blockIdx.x;
    const float* src = (d < TC) ? (Wv + (size_t)d * TC) : bv;
    float s = 0.0f;
    for (int c = threadIdx.x; c < TC; c += 256) s += src[c];
    s = blk_reduce_sum(s, sbuf);
    if (threadIdx.x == 0) out[d] = s;
}
__global__ void vsum_kernel(const float* __restrict__ x, const float* __restrict__ wvs,
                            float* __restrict__ out)
{
    __shared__ float sbuf[32];
    int row = blockIdx.x;
    const float* xr = x + (size_t)row * TC;
    float s = 0.0f;
    for (int c = threadIdx.x; c < TC; c += 256) s += xr[c] * wvs[c];
    s = blk_reduce_sum(s, sbuf);
    if (threadIdx.x == 0) out[row] = s + wvs[TC];
}
__global__ void init_tw_kernel(float2* __restrict__ tw)
{
    int j = blockIdx.x * 256 + threadIdx.x;
    float sv, cv;
    sincosf(-6.283185307179586f * ((float)j * (1.0f / 2048.0f)), &sv, &cv);
    tw[j] = make_float2(cv, sv);
}

// ===================== FFT correlation + softmax + *vsum =====================
// radix-4 DIT pass: fuses two consecutive radix-2 stages (halves H and 2H).
// Input in bit-reversed order (as for radix-2 DIT); identical math, half the passes.
template<int H>
__device__ __forceinline__ void fft_r4_pass(float2* z, const float2* tw, int tid, bool inv)
{
    #pragma unroll
    for (int jj = 0; jj < 2; jj++) {
        int j = tid + jj * 256;              // 512 quads
        int grp = j / H;
        int p = j & (H - 1);
        int i0 = grp * 4 * H + p;
        float2 w1 = tw[p * (1024 / H)];      // e^{-2pi i p/(2H)}
        float2 w2 = tw[p * (512 / H)];       // e^{-2pi i p/(4H)}
        if (inv) { w1.y = -w1.y; w2.y = -w2.y; }
        float2 z0 = z[i0], z1 = z[i0+H], z2 = z[i0+2*H], z3 = z[i0+3*H];
        float2 t1 = make_float2(w1.x*z1.x - w1.y*z1.y, w1.x*z1.y + w1.y*z1.x);
        float2 a0 = make_float2(z0.x + t1.x, z0.y + t1.y);
        float2 a1 = make_float2(z0.x - t1.x, z0.y - t1.y);
        float2 t3 = make_float2(w1.x*z3.x - w1.y*z3.y, w1.x*z3.y + w1.y*z3.x);
        float2 a2 = make_float2(z2.x + t3.x, z2.y + t3.y);
        float2 a3 = make_float2(z2.x - t3.x, z2.y - t3.y);
        float2 t2 = make_float2(w2.x*a2.x - w2.y*a2.y, w2.x*a2.y + w2.y*a2.x);
        float2 t4 = make_float2(w2.x*a3.x - w2.y*a3.y, w2.x*a3.y + w2.y*a3.x);
        // w2' = -i*w2 (fwd) / +i*conj(w2) (inv)
        float2 u = inv ? make_float2(-t4.y, t4.x) : make_float2(t4.y, -t4.x);
        z[i0]       = make_float2(a0.x + t2.x, a0.y + t2.y);
        z[i0+H]     = make_float2(a1.x + u.x,  a1.y + u.y);
        z[i0+2*H]   = make_float2(a0.x - t2.x, a0.y - t2.y);
        z[i0+3*H]   = make_float2(a1.x - u.x,  a1.y - u.y);
    }
}

__device__ __forceinline__ void fft_all(float2* z, const float2* tw, int tid, bool inv)
{
    fft_r4_pass<1>(z, tw, tid, inv);   __syncthreads();
    fft_r4_pass<4>(z, tw, tid, inv);   __syncthreads();
    fft_r4_pass<16>(z, tw, tid, inv);  __syncthreads();
    fft_r4_pass<64>(z, tw, tid, inv);  __syncthreads();
    fft_r4_pass<256>(z, tw, tid, inv); __syncthreads();
    // final radix-2 stage, half = 1024
    #pragma unroll
    for (int jj = 0; jj < 4; jj++) {
        int j = tid + jj * 256;
        float2 w = tw[j];
        if (inv) w.y = -w.y;
        float2 u = z[j], v = z[j + 1024];
        float2 t = make_float2(w.x*v.x - w.y*v.y, w.x*v.y + w.y*v.x);
        z[j]        = make_float2(u.x + t.x, u.y + t.y);
        z[j + 1024] = make_float2(u.x - t.x, u.y - t.y);
    }
    __syncthreads();
}

__global__ void __launch_bounds__(256)
fft_corr_softmax(const float* qt, const float* kt,
                 const float* __restrict__ vsum, const float2* __restrict__ gtw,
                 float* attn_t)
{
    __shared__ float2 z[2048];
    __shared__ float2 tw[1024];
    __shared__ float sbuf[32];

    const int bc = blockIdx.x;
    const int b = bc >> 10;
    const int tid = threadIdx.x;
    const float* qrow = qt + (size_t)bc * TT;
    const float* krow = kt + (size_t)bc * TT;

    #pragma unroll
    for (int i = 0; i < 2; i++) {
        int j = tid + i * 256;
        ((float4*)tw)[j] = __ldg((const float4*)gtw + j);
    }
    // load z = q + i*k, bit-reversed
    #pragma unroll
    for (int i = 0; i < 8; i++) {
        int t = tid + i * 256;
        int r = __brev((unsigned)t) >> 21;
        z[r] = make_float2(qrow[t], krow[t]);
    }
    __syncthreads();

    fft_all(z, tw, tid, false);          // forward, natural-order spectrum

    // P(f) = Q(f) * conj(K(f)); Hermitian split of packed transform
    for (int f = tid; f <= 1024; f += 256) {
        int g = (2048 - f) & 2047;
        float2 zf = z[f], zg = z[g];
        float Qr = 0.5f * (zf.x + zg.x);
        float Qi = 0.5f * (zf.y - zg.y);
        float Kr = 0.5f * (zf.y + zg.y);
        float Ki = 0.5f * (zg.x - zf.x);
        float Pr = Qr * Kr + Qi * Ki;
        float Pi = Qi * Kr - Qr * Ki;
        z[f] = make_float2(Pr, Pi);
        z[g] = make_float2(Pr, -Pi);
    }
    __syncthreads();

    // bit-reverse permute, then inverse transform
    #pragma unroll
    for (int i = 0; i < 8; i++) {
        int t = tid + i * 256;
        int r = __brev((unsigned)t) >> 21;
        if (r > t) { float2 a = z[t]; z[t] = z[r]; z[r] = a; }
    }
    __syncthreads();
    fft_all(z, tw, tid, true);

    // corr[t] = Re(z[t]) / N ; softmax over t; attn = w * vsum[b,t]
    float cvals[8];
    float vmax = -CUDART_INF_F;
    #pragma unroll
    for (int i = 0; i < 8; i++) {
        int t = tid + i * 256;
        cvals[i] = z[t].x * (1.0f / 2048.0f);
        vmax = fmaxf(vmax, cvals[i]);
    }
    vmax = blk_reduce_max(vmax, sbuf);
    float ssum = 0.0f;
    #pragma unroll
    for (int i = 0; i < 8; i++) {
        cvals[i] = expf(cvals[i] - vmax);
        ssum += cvals[i];
    }
    ssum = blk_reduce_sum(ssum, sbuf);
    float inv = 1.0f / ssum;

    const float* vs = vsum + (size_t)b * TT;
    float* arow = attn_t + (size_t)bc * TT;
    #pragma unroll
    for (int i = 0; i < 8; i++) {
        int t = tid + i * 256;
        arow[t] = cvals[i] * inv * vs[t];
    }
}

// ===================== transpose [B,C,T] -> [B,T,C] =====================
__global__ void transpose_kernel(const float* __restrict__ in, float* __restrict__ out)
{
    __shared__ float tile[32][33];
    int b = blockIdx.z;
    int t0 = blockIdx.x * 32;
    int c0 = blockIdx.y * 32;
    const float* inb = in + (size_t)b * TC * TT;
    float* outb = out + (size_t)b * TT * TC;
    #pragma unroll
    for (int y = threadIdx.y; y < 32; y += 8)
        tile[y][threadIdx.x] = inb[(size_t)(c0 + y) * TT + t0 + threadIdx.x];
    __syncthreads();
    #pragma unroll
    for (int y = threadIdx.y; y < 32; y += 8)
        outb[(size_t)(t0 + y) * TC + c0 + threadIdx.x] = tile[threadIdx.x][y];
}

// ===================== residual + layernorm (opt chunked split output) =====================
template<int SPLIT>
__global__ void __launch_bounds__(256)
add_ln_kernel(const float* __restrict__ x, const float* __restrict__ r,
              const float* __restrict__ g, const float* __restrict__ be,
              float* __restrict__ out,
              __nv_bfloat16* __restrict__ ohi, __nv_bfloat16* __restrict__ olo)
{
    __shared__ float sbuf[32];
    int row = blockIdx.x;
    const float* xr = x + (size_t)row * TC;
    const float* rr = r + (size_t)row * TC;
    int tid = threadIdx.x;

    float v[4];
    float s = 0.0f;
    #pragma unroll
    for (int i = 0; i < 4; i++) {
        int c = i * 256 + tid;
        v[i] = xr[c] + rr[c];
        s += v[i];
    }
    s = blk_reduce_sum(s, sbuf);
    float mean = s * (1.0f / (float)TC);
    float sq = 0.0f;
    #pragma unroll
    for (int i = 0; i < 4; i++) {
        float d = v[i] - mean;
        sq += d * d;
    }
    sq = blk_reduce_sum(sq, sbuf);
    float rstd = rsqrtf(sq * (1.0f / (float)TC) + 1e-5f);
    #pragma unroll
    for (int i = 0; i < 4; i++) {
        int c = i * 256 + tid;
        float y = (v[i] - mean) * rstd * g[c] + be[c];
        out[(size_t)row * TC + c] = y;
        if (SPLIT) {
            __nv_bfloat16 h = __float2bfloat16(y);
            size_t pos = chunked_pos(row, c, TM_TOTAL);
            ohi[pos] = h;
            olo[pos] = __float2bfloat16(y - __bfloat162float(h));
        }
    }
}

// ===================== launcher =====================
extern "C" void kernel_launch(void* const* d_in, const int* in_sizes, int n_in,
                              void* d_out, int out_size)
{
    const float* x   = (const float*)d_in[0];
    const float* Wq  = (const float*)d_in[1];
    const float* bq  = (const float*)d_in[2];
    const float* Wk  = (const float*)d_in[3];
    const float* bk  = (const float*)d_in[4];
    const float* Wv  = (const float*)d_in[5];
    const float* bv  = (const float*)d_in[6];
    const float* g1  = (const float*)d_in[7];
    const float* be1 = (const float*)d_in[8];
    const float* W1  = (const float*)d_in[9];
    const float* bf1 = (const float*)d_in[10];
    const float* W2  = (const float*)d_in[11];
    const float* bf2 = (const float*)d_in[12];
    const float* g2  = (const float*)d_in[13];
    const float* be2 = (const float*)d_in[14];

    float *buf0, *buf1, *y1, *vsum, *wvs;
    float2* tw;
    __nv_bfloat16 *xhi, *xlo, *y1hi, *y1lo, *h1hi, *h1lo, *wthi, *wtlo;
    cudaGetSymbolAddress((void**)&buf0, g_buf0);
    cudaGetSymbolAddress((void**)&buf1, g_buf1);
    cudaGetSymbolAddress((void**)&y1,   g_y1);
    cudaGetSymbolAddress((void**)&vsum, g_vsum);
    cudaGetSymbolAddress((void**)&wvs,  g_wvs);
    cudaGetSymbolAddress((void**)&tw,   g_tw);
    cudaGetSymbolAddress((void**)&xhi,  g_xhi);
    cudaGetSymbolAddress((void**)&xlo,  g_xlo);
    cudaGetSymbolAddress((void**)&y1hi, g_y1hi);
    cudaGetSymbolAddress((void**)&y1lo, g_y1lo);
    cudaGetSymbolAddress((void**)&h1hi, g_h1hi);
    cudaGetSymbolAddress((void**)&h1lo, g_h1lo);
    cudaGetSymbolAddress((void**)&wthi, g_wthi);
    cudaGetSymbolAddress((void**)&wtlo, g_wtlo);

    cudaFuncSetAttribute(gemm_tc<0>, cudaFuncAttributeMaxDynamicSharedMemorySize, GEMM_SMEM);
    cudaFuncSetAttribute(gemm_tc<1>, cudaFuncAttributeMaxDynamicSharedMemorySize, GEMM_SMEM);
    cudaFuncSetAttribute(gemm_tc<2>, cudaFuncAttributeMaxDynamicSharedMemorySize, GEMM_SMEM);

    const int M = TM_TOTAL;
    const size_t WSTRIDE = (size_t)TC * TC;
    dim3 wgrid(32, 32), wblk(32, 8);
    dim3 ggrid(TC / BN, M / BM);   // (8, 128)

    // prep: twiddles, split x, transpose+split weights (into chunked-swizzled layouts)
    init_tw_kernel<<<4, 256>>>(tw);
    split_kernel<<<(M * TC) / (256 * 4), 256>>>(x, xhi, xlo);
    transpose_split_w<<<wgrid, wblk>>>(Wq, wthi + 0*WSTRIDE, wtlo + 0*WSTRIDE);
    transpose_split_w<<<wgrid, wblk>>>(Wk, wthi + 1*WSTRIDE, wtlo + 1*WSTRIDE);
    transpose_split_w<<<wgrid, wblk>>>(W1, wthi + 2*WSTRIDE, wtlo + 2*WSTRIDE);
    transpose_split_w<<<wgrid, wblk>>>(W2, wthi + 3*WSTRIDE, wtlo + 3*WSTRIDE);

    // v channel-sum collapses to a GEMV
    wvsum_kernel<<<TC + 1, 256>>>(Wv, bv, wvs);
    vsum_kernel<<<M, 256>>>(x, wvs, vsum);

    // q_t, k_t in [B,C,T] via tensor-core GEMM with transposed epilogue
    gemm_tc<1><<<ggrid, 256, GEMM_SMEM>>>(xhi, xlo, wthi + 0*WSTRIDE, wtlo + 0*WSTRIDE, bq, buf0, nullptr, nullptr);
    gemm_tc<1><<<ggrid, 256, GEMM_SMEM>>>(xhi, xlo, wthi + 1*WSTRIDE, wtlo + 1*WSTRIDE, bk, buf1, nullptr, nullptr);

    // FFT xcorr + softmax + *vsum
    fft_corr_softmax<<<TB * TC, 256>>>(buf0, buf1, vsum, tw, buf0);

    // attn_t [B,C,T] -> attn [B,T,C]
    transpose_kernel<<<dim3(TT / 32, TC / 32, TB), dim3(32, 8)>>>(buf0, buf1);

    // LN1 (emits fp32 + chunked bf16 hi/lo)
    add_ln_kernel<1><<<M, 256>>>(x, buf1, g1, be1, y1, y1hi, y1lo);

    // FFN
    gemm_tc<2><<<ggrid, 256, GEMM_SMEM>>>(y1hi, y1lo, wthi + 2*WSTRIDE, wtlo + 2*WSTRIDE, bf1, nullptr, h1hi, h1lo);
    gemm_tc<0><<<ggrid, 256, GEMM_SMEM>>>(h1hi, h1lo, wthi + 3*WSTRIDE, wtlo + 3*WSTRIDE, bf2, buf0, nullptr, nullptr);

    // LN2 -> out
    add_ln_kernel<0><<<M, 256>>>(y1, buf0, g2, be2, (float*)d_out, nullptr, nullptr);
}